// round 2
// baseline (speedup 1.0000x reference)
#include <cuda_runtime.h>
#include <cstdint>
#include <math.h>

#define T_STEPS 512
#define BATCH   64
#define DIN     1024
#define HID     128
#define GATES   512   // 4*HID

// Scratch: x1[t][b][g] = feats @ W_ih1^T + b_ih1 + b_hh1   (64 MB)
__device__ float g_x1[(size_t)T_STEPS * BATCH * GATES];

__device__ __forceinline__ float sigmoidf_(float x){
    return 1.0f / (1.0f + __expf(-x));
}

// ---------------------------------------------------------------------------
// Kernel 1: x1 GEMM.  A = feats [32768,1024] row-major, W = W_ih1 [512,1024].
// Block tile 128x128, K-chunk 8, 256 threads, 8x8 micro-tile (strided layout
// for conflict-free smem reads). Epilogue adds b_ih1+b_hh1 and writes
// g_x1[t][b][g] (t = m%512, b = m/512).
// ---------------------------------------------------------------------------
__global__ __launch_bounds__(256, 2) void x1_gemm_kernel(
    const float* __restrict__ A,
    const float* __restrict__ W,
    const float* __restrict__ bih,
    const float* __restrict__ bhh)
{
    const int LD = 132;                 // pad: conflict-free transposed stores
    __shared__ float As[8][LD];
    __shared__ float Bs[8][LD];

    const int tid = threadIdx.x;
    const int tx  = tid & 15;
    const int ty  = tid >> 4;
    const int m0  = blockIdx.y << 7;
    const int n0  = blockIdx.x << 7;

    const int lrow = tid >> 1;          // 0..127
    const int lk4  = (tid & 1) << 2;    // 0 or 4

    const float* Ap = A + (size_t)(m0 + lrow) * DIN + lk4;
    const float* Wp = W + (size_t)(n0 + lrow) * DIN + lk4;

    float acc[8][8];
    #pragma unroll
    for (int i = 0; i < 8; i++)
        #pragma unroll
        for (int j2 = 0; j2 < 8; j2++) acc[i][j2] = 0.f;

    for (int k0 = 0; k0 < DIN; k0 += 8){
        float4 av = *reinterpret_cast<const float4*>(Ap + k0);
        float4 wv = *reinterpret_cast<const float4*>(Wp + k0);
        __syncthreads();
        As[lk4+0][lrow] = av.x; As[lk4+1][lrow] = av.y;
        As[lk4+2][lrow] = av.z; As[lk4+3][lrow] = av.w;
        Bs[lk4+0][lrow] = wv.x; Bs[lk4+1][lrow] = wv.y;
        Bs[lk4+2][lrow] = wv.z; Bs[lk4+3][lrow] = wv.w;
        __syncthreads();
        #pragma unroll
        for (int kk = 0; kk < 8; kk++){
            float a[8], b[8];
            #pragma unroll
            for (int i = 0; i < 8; i++)  a[i]  = As[kk][ty + 16*i];   // 2-addr broadcast
            #pragma unroll
            for (int j2 = 0; j2 < 8; j2++) b[j2] = Bs[kk][tx + 16*j2]; // consecutive lanes
            #pragma unroll
            for (int i = 0; i < 8; i++)
                #pragma unroll
                for (int j2 = 0; j2 < 8; j2++)
                    acc[i][j2] = fmaf(a[i], b[j2], acc[i][j2]);
        }
    }

    float bias[8];
    #pragma unroll
    for (int j2 = 0; j2 < 8; j2++){
        int n = n0 + tx + 16*j2;
        bias[j2] = bih[n] + bhh[n];
    }
    #pragma unroll
    for (int i = 0; i < 8; i++){
        int m = m0 + ty + 16*i;
        int b = m >> 9;          // batch
        int t = m & 511;         // timestep
        float* dst = g_x1 + ((size_t)t * BATCH + b) * GATES + n0 + tx;
        #pragma unroll
        for (int j2 = 0; j2 < 8; j2++)
            dst[16*j2] = acc[i][j2] + bias[j2];
    }
}

// ---------------------------------------------------------------------------
// Kernel 2: recurrence. 32 independent clusters of 4 CTAs (128 CTAs total),
// 256 threads/CTA. Cluster c owns batches {2c, 2c+1}. CTA rank r owns
// j-slice [32r,32r+32) of every gate of both layers; its weight rows live in
// registers (w1/w2/w3 = 192 floats/thread). h1/h2 double-buffered in smem,
// slices broadcast to the 4 cluster CTAs via st.shared::cluster; two
// barrier.cluster syncs per timestep. No inter-cluster communication.
// ---------------------------------------------------------------------------
__global__ void __cluster_dims__(4,1,1) __launch_bounds__(256, 1)
lstm_rec_kernel(const float* __restrict__ Whh1,
                const float* __restrict__ Wih2,
                const float* __restrict__ Whh2,
                const float* __restrict__ bih2,
                const float* __restrict__ bhh2,
                float* __restrict__ out)
{
    __shared__ float h1s[2][2][HID];    // [parity][local b][h]
    __shared__ float h2s[2][2][HID];
    __shared__ float c1s[2][32];        // [local b][local j] (owned slice)
    __shared__ float c2s[2][32];
    __shared__ float ps[256][2];        // partial sums [tid][local b]
    __shared__ float b2s[128];          // b_ih2+b_hh2 for this CTA's rows

    const int tid  = threadIdx.x;
    const int j    = tid & 31;
    const int q    = (tid >> 5) & 3;    // gate: 0=i 1=f 2=g 3=o
    const int half = tid >> 7;          // k-range half
    uint32_t rank;
    asm("mov.u32 %0, %%cluster_ctarank;" : "=r"(rank));
    const int b0   = (blockIdx.x >> 2) * 2;               // first batch of cluster
    const int grow = q * 128 + (int)rank * 32 + j;        // global gate row

    // Load register-resident weight slices (64 floats of each matrix/thread).
    float w1[64], w2[64], w3[64];
    {
        const float4* p1 = reinterpret_cast<const float4*>(Whh1 + (size_t)grow * HID + half * 64);
        const float4* p2 = reinterpret_cast<const float4*>(Wih2 + (size_t)grow * HID + half * 64);
        const float4* p3 = reinterpret_cast<const float4*>(Whh2 + (size_t)grow * HID + half * 64);
        #pragma unroll
        for (int k = 0; k < 16; k++){
            float4 v1 = p1[k], v2 = p2[k], v3 = p3[k];
            w1[4*k+0]=v1.x; w1[4*k+1]=v1.y; w1[4*k+2]=v1.z; w1[4*k+3]=v1.w;
            w2[4*k+0]=v2.x; w2[4*k+1]=v2.y; w2[4*k+2]=v2.z; w2[4*k+3]=v2.w;
            w3[4*k+0]=v3.x; w3[4*k+1]=v3.y; w3[4*k+2]=v3.z; w3[4*k+3]=v3.w;
        }
    }

    // Init state
    for (int i = tid; i < 2*2*HID; i += 256){
        (&h1s[0][0][0])[i] = 0.f;
        (&h2s[0][0][0])[i] = 0.f;
    }
    if (tid < 64){ c1s[tid>>5][tid&31] = 0.f; c2s[tid>>5][tid&31] = 0.f; }
    if (tid < 128){
        int rr = (tid >> 5) * 128 + (int)rank * 32 + (tid & 31);
        b2s[tid] = bih2[rr] + bhh2[rr];
    }
    __syncthreads();
    asm volatile("barrier.cluster.arrive.aligned;" ::: "memory");
    asm volatile("barrier.cluster.wait.aligned;"   ::: "memory");

    int cur = 0;
    for (int t = 0; t < T_STEPS; t++){
        const int nxt = cur ^ 1;

        // x1 prefetch (only half==0 threads fold it in)
        float xv0 = 0.f, xv1 = 0.f;
        if (half == 0){
            const float* xp = g_x1 + ((size_t)t * BATCH + b0) * GATES + grow;
            xv0 = xp[0];
            xv1 = xp[GATES];
        }

        // ---- layer 1 partial dots (weights in regs, h broadcast from smem)
        float p0 = 0.f, p1 = 0.f;
        {
            const float* hv0 = &h1s[cur][0][half * 64];
            const float* hv1 = &h1s[cur][1][half * 64];
            #pragma unroll
            for (int k = 0; k < 64; k++){
                p0 = fmaf(w1[k], hv0[k], p0);
                p1 = fmaf(w1[k], hv1[k], p1);
            }
        }
        ps[tid][0] = p0 + xv0;
        ps[tid][1] = p1 + xv1;
        __syncthreads();
        if (tid < 64){
            const int b = tid >> 5, jj = tid & 31;
            float pre0 = ps[      jj][b] + ps[128 + jj][b];
            float pre1 = ps[ 32 + jj][b] + ps[160 + jj][b];
            float pre2 = ps[ 64 + jj][b] + ps[192 + jj][b];
            float pre3 = ps[ 96 + jj][b] + ps[224 + jj][b];
            float c = sigmoidf_(pre1) * c1s[b][jj] + sigmoidf_(pre0) * tanhf(pre2);
            c1s[b][jj] = c;
            float h = sigmoidf_(pre3) * tanhf(c);
            uint32_t la = (uint32_t)__cvta_generic_to_shared(&h1s[nxt][b][(int)rank * 32 + jj]);
            #pragma unroll
            for (int pr = 0; pr < 4; pr++){
                uint32_t ra;
                asm volatile("mapa.shared::cluster.u32 %0, %1, %2;" : "=r"(ra) : "r"(la), "r"(pr));
                asm volatile("st.shared::cluster.f32 [%0], %1;" :: "r"(ra), "f"(h) : "memory");
            }
        }
        asm volatile("barrier.cluster.arrive.aligned;" ::: "memory");
        asm volatile("barrier.cluster.wait.aligned;"   ::: "memory");

        // ---- layer 2 partial dots
        p0 = 0.f; p1 = 0.f;
        {
            const float* a0 = &h1s[nxt][0][half * 64];
            const float* a1 = &h1s[nxt][1][half * 64];
            const float* d0 = &h2s[cur][0][half * 64];
            const float* d1 = &h2s[cur][1][half * 64];
            #pragma unroll
            for (int k = 0; k < 64; k++){
                p0 = fmaf(w2[k], a0[k], p0);
                p1 = fmaf(w2[k], a1[k], p1);
                p0 = fmaf(w3[k], d0[k], p0);
                p1 = fmaf(w3[k], d1[k], p1);
            }
        }
        ps[tid][0] = p0;
        ps[tid][1] = p1;
        __syncthreads();
        if (tid < 64){
            const int b = tid >> 5, jj = tid & 31;
            float pre0 = ps[      jj][b] + ps[128 + jj][b] + b2s[      jj];
            float pre1 = ps[ 32 + jj][b] + ps[160 + jj][b] + b2s[ 32 + jj];
            float pre2 = ps[ 64 + jj][b] + ps[192 + jj][b] + b2s[ 64 + jj];
            float pre3 = ps[ 96 + jj][b] + ps[224 + jj][b] + b2s[ 96 + jj];
            float c = sigmoidf_(pre1) * c2s[b][jj] + sigmoidf_(pre0) * tanhf(pre2);
            c2s[b][jj] = c;
            float h = sigmoidf_(pre3) * tanhf(c);
            uint32_t la = (uint32_t)__cvta_generic_to_shared(&h2s[nxt][b][(int)rank * 32 + jj]);
            #pragma unroll
            for (int pr = 0; pr < 4; pr++){
                uint32_t ra;
                asm volatile("mapa.shared::cluster.u32 %0, %1, %2;" : "=r"(ra) : "r"(la), "r"(pr));
                asm volatile("st.shared::cluster.f32 [%0], %1;" :: "r"(ra), "f"(h) : "memory");
            }
            out[((size_t)(b0 + b) * T_STEPS + t) * HID + (int)rank * 32 + jj] = h;
        }
        asm volatile("barrier.cluster.arrive.aligned;" ::: "memory");
        asm volatile("barrier.cluster.wait.aligned;"   ::: "memory");

        cur = nxt;
    }
}

// ---------------------------------------------------------------------------
extern "C" void kernel_launch(void* const* d_in, const int* in_sizes, int n_in,
                              void* d_out, int out_size)
{
    (void)in_sizes; (void)n_in; (void)out_size;
    const float* feats = (const float*)d_in[0];
    const float* W_ih1 = (const float*)d_in[1];
    const float* W_hh1 = (const float*)d_in[2];
    const float* b_ih1 = (const float*)d_in[3];
    const float* b_hh1 = (const float*)d_in[4];
    const float* W_ih2 = (const float*)d_in[5];
    const float* W_hh2 = (const float*)d_in[6];
    const float* b_ih2 = (const float*)d_in[7];
    const float* b_hh2 = (const float*)d_in[8];
    float* out = (float*)d_out;

    dim3 g1(GATES / 128, (BATCH * T_STEPS) / 128);   // (4, 256)
    x1_gemm_kernel<<<g1, 256>>>(feats, W_ih1, b_ih1, b_hh1);

    lstm_rec_kernel<<<128, 256>>>(W_hh1, W_ih2, W_hh2, b_ih2, b_hh2, out);
}

// round 6
// speedup vs baseline: 2.1554x; 2.1554x over previous
#include <cuda_runtime.h>
#include <cuda_bf16.h>
#include <cstdint>

#define T_STEPS 512
#define BATCH   64
#define DIN     1024
#define HID     128
#define GATES   512   // 4*HID

// Scratch: x1[t][b][g] = feats @ W_ih1^T + b_ih1 + b_hh1   (64 MB)
__device__ float g_x1[(size_t)T_STEPS * BATCH * GATES];

// ---------------------------------------------------------------------------
// helpers
// ---------------------------------------------------------------------------
__device__ __forceinline__ uint32_t s2u(const void* p){
    uint32_t a;
    asm("{ .reg .u64 t; cvta.to.shared.u64 t, %1; cvt.u32.u64 %0, t; }" : "=r"(a) : "l"(p));
    return a;
}
__device__ __forceinline__ float sigmoidf_(float x){
    return 1.0f / (1.0f + __expf(-x));
}
__device__ __forceinline__ void ldsm4(uint32_t* r, uint32_t addr){
    asm volatile("ldmatrix.sync.aligned.m8n8.x4.shared.b16 {%0,%1,%2,%3}, [%4];"
        : "=r"(r[0]), "=r"(r[1]), "=r"(r[2]), "=r"(r[3]) : "r"(addr));
}
__device__ __forceinline__ void mma16816(float* c, const uint32_t* a, const uint32_t* b){
    asm volatile("mma.sync.aligned.m16n8k16.row.col.f32.bf16.bf16.f32 "
        "{%0,%1,%2,%3}, {%4,%5,%6,%7}, {%8,%9}, {%0,%1,%2,%3};"
        : "+f"(c[0]), "+f"(c[1]), "+f"(c[2]), "+f"(c[3])
        : "r"(a[0]), "r"(a[1]), "r"(a[2]), "r"(a[3]), "r"(b[0]), "r"(b[1]));
}
// hi bf16 pair = truncated top-16 bits of (x,y)
__device__ __forceinline__ uint2 hi_pair(float4 v){
    uint32_t x = __float_as_uint(v.x), y = __float_as_uint(v.y);
    uint32_t z = __float_as_uint(v.z), w = __float_as_uint(v.w);
    uint32_t h0, h1;
    asm("prmt.b32 %0, %1, %2, 0x7632;" : "=r"(h0) : "r"(x), "r"(y));
    asm("prmt.b32 %0, %1, %2, 0x7632;" : "=r"(h1) : "r"(z), "r"(w));
    return make_uint2(h0, h1);
}
// lo residual pair (exact subtract of truncated hi, then rn to bf16)
__device__ __forceinline__ uint2 lo_pair(float4 v){
    float lx = v.x - __uint_as_float(__float_as_uint(v.x) & 0xFFFF0000u);
    float ly = v.y - __uint_as_float(__float_as_uint(v.y) & 0xFFFF0000u);
    float lz = v.z - __uint_as_float(__float_as_uint(v.z) & 0xFFFF0000u);
    float lw = v.w - __uint_as_float(__float_as_uint(v.w) & 0xFFFF0000u);
    uint32_t l0, l1;
    asm("cvt.rn.bf16x2.f32 %0, %1, %2;" : "=r"(l0) : "f"(ly), "f"(lx));
    asm("cvt.rn.bf16x2.f32 %0, %1, %2;" : "=r"(l1) : "f"(lw), "f"(lz));
    return make_uint2(l0, l1);
}
__device__ __forceinline__ unsigned long long fma2(unsigned long long a,
        unsigned long long b, unsigned long long c){
    unsigned long long d;
    asm("fma.rn.f32x2 %0, %1, %2, %3;" : "=l"(d) : "l"(a), "l"(b), "l"(c));
    return d;
}
__device__ __forceinline__ unsigned long long packf2(float x, float y){
    unsigned long long r;
    asm("mov.b64 %0, {%1, %2};" : "=l"(r) : "f"(x), "f"(y));
    return r;
}
__device__ __forceinline__ float hsum2(unsigned long long v){
    return __uint_as_float((uint32_t)v) + __uint_as_float((uint32_t)(v >> 32));
}

// ---------------------------------------------------------------------------
// Kernel 1: x1 GEMM via split-bf16 mma.sync (3 passes: hh + lh + hl).
// CTA tile 128x128, K-chunk 32, 8 warps (4x2), warp tile 32x64.
// smem: pitch-80B bf16 tiles, double buffered (80KB dynamic).
// ---------------------------------------------------------------------------
#define PITCH 80
#define TILE_B (128 * PITCH)      // 10240
#define O_AHI 0
#define O_ALO (1 * TILE_B)
#define O_BHI (2 * TILE_B)
#define O_BLO (3 * TILE_B)
#define BUFB  (4 * TILE_B)        // 40960
#define GSMEM (2 * BUFB)          // 81920

__global__ __launch_bounds__(256, 1) void x1_gemm_hmma(
    const float* __restrict__ A,
    const float* __restrict__ W,
    const float* __restrict__ bih,
    const float* __restrict__ bhh)
{
    extern __shared__ __align__(128) char smg[];
    __shared__ float biasS[128];
    const int tid  = threadIdx.x;
    const int lane = tid & 31, wid = tid >> 5;
    const int wm = wid & 3, wn = wid >> 2;
    const int m0 = blockIdx.y << 7, n0 = blockIdx.x << 7;

    if (tid < 128) biasS[tid] = bih[n0 + tid] + bhh[n0 + tid];

    const int lrow = tid >> 3;          // 0..31 (row within 32-row stripe)
    const int lc4  = tid & 7;           // float4 column
    const float* Abase = A + (size_t)(m0 + lrow) * DIN + lc4 * 4;
    const float* Wbase = W + (size_t)(n0 + lrow) * DIN + lc4 * 4;
    const int soff = lrow * PITCH + lc4 * 8;

    const uint32_t sbase = s2u(smg);
    const uint32_t a_off = (uint32_t)((wm * 32 + (lane & 15)) * PITCH + (lane >> 4) * 16);
    const uint32_t b_off = (uint32_t)((wn * 64 + (lane & 7) + 8 * (lane >> 4)) * PITCH
                                      + ((lane >> 3) & 1) * 16);

    float c[2][8][4];
    #pragma unroll
    for (int i = 0; i < 2; i++)
        #pragma unroll
        for (int j = 0; j < 8; j++)
            #pragma unroll
            for (int k = 0; k < 4; k++) c[i][j][k] = 0.f;

    float4 ra[4], rw[4];
    #pragma unroll
    for (int i = 0; i < 4; i++){
        ra[i] = *(const float4*)(Abase + (size_t)(32 * i) * DIN);
        rw[i] = *(const float4*)(Wbase + (size_t)(32 * i) * DIN);
    }
    #pragma unroll
    for (int i = 0; i < 4; i++){
        int off = soff + i * 32 * PITCH;
        *(uint2*)(smg + O_AHI + off) = hi_pair(ra[i]);
        *(uint2*)(smg + O_ALO + off) = lo_pair(ra[i]);
        *(uint2*)(smg + O_BHI + off) = hi_pair(rw[i]);
        *(uint2*)(smg + O_BLO + off) = lo_pair(rw[i]);
    }
    __syncthreads();

    for (int ci = 0; ci < 32; ci++){
        const uint32_t buf = sbase + (uint32_t)(ci & 1) * BUFB;
        if (ci < 31){
            #pragma unroll
            for (int i = 0; i < 4; i++){
                ra[i] = *(const float4*)(Abase + (size_t)(32 * i) * DIN + (ci + 1) * 32);
                rw[i] = *(const float4*)(Wbase + (size_t)(32 * i) * DIN + (ci + 1) * 32);
            }
        }
        #pragma unroll
        for (int kk = 0; kk < 2; kk++){
            uint32_t ah0[4], ah1[4], al0[4], al1[4], bh[4][4], bl[4][4];
            const uint32_t ka = a_off + kk * 32;
            const uint32_t kb = b_off + kk * 32;
            ldsm4(ah0, buf + O_AHI + ka);
            ldsm4(ah1, buf + O_AHI + ka + 16 * PITCH);
            ldsm4(al0, buf + O_ALO + ka);
            ldsm4(al1, buf + O_ALO + ka + 16 * PITCH);
            #pragma unroll
            for (int q2 = 0; q2 < 4; q2++){
                ldsm4(bh[q2], buf + O_BHI + kb + q2 * 16 * PITCH);
                ldsm4(bl[q2], buf + O_BLO + kb + q2 * 16 * PITCH);
            }
            #pragma unroll
            for (int nt = 0; nt < 8; nt++){
                const uint32_t* bhp = &bh[nt >> 1][(nt & 1) * 2];
                const uint32_t* blp = &bl[nt >> 1][(nt & 1) * 2];
                mma16816(c[0][nt], ah0, bhp);
                mma16816(c[1][nt], ah1, bhp);
                mma16816(c[0][nt], al0, bhp);
                mma16816(c[1][nt], al1, bhp);
                mma16816(c[0][nt], ah0, blp);
                mma16816(c[1][nt], ah1, blp);
            }
        }
        if (ci < 31){
            char* b = smg + ((ci + 1) & 1) * BUFB;
            #pragma unroll
            for (int i = 0; i < 4; i++){
                int off = soff + i * 32 * PITCH;
                *(uint2*)(b + O_AHI + off) = hi_pair(ra[i]);
                *(uint2*)(b + O_ALO + off) = lo_pair(ra[i]);
                *(uint2*)(b + O_BHI + off) = hi_pair(rw[i]);
                *(uint2*)(b + O_BLO + off) = lo_pair(rw[i]);
            }
        }
        __syncthreads();
    }

    // epilogue: C frag (m16n8): c0/c1 row=lane/4, cols 2(lane%4)+{0,1}; c2/c3 row+8
    const int gr = lane >> 2;
    const int gc = (lane & 3) * 2;
    #pragma unroll
    for (int mt = 0; mt < 2; mt++){
        #pragma unroll
        for (int nt = 0; nt < 8; nt++){
            const int n = wn * 64 + nt * 8 + gc;
            const float b0 = biasS[n], b1 = biasS[n + 1];
            #pragma unroll
            for (int rr = 0; rr < 2; rr++){
                const int m = m0 + wm * 32 + mt * 16 + gr + rr * 8;
                const int bb = m >> 9;
                const int tt = m & 511;
                float2 o = make_float2(c[mt][nt][rr * 2 + 0] + b0,
                                       c[mt][nt][rr * 2 + 1] + b1);
                *(float2*)(g_x1 + ((size_t)tt * BATCH + bb) * GATES + n0 + n) = o;
            }
        }
    }
}

// ---------------------------------------------------------------------------
// Kernel 2: fused recurrence. 32 clusters x 4 CTAs, 2 batches/cluster,
// ONE cluster barrier per timestep. Dot products use fma.rn.f32x2 (packed
// k-pairs; h pairs loaded directly as b64 from smem, weights pre-packed in
// b64 registers). Gates: exact __expf/tanhf (proven 3e-7 in round 1).
// ---------------------------------------------------------------------------
__device__ __forceinline__ void bcast4(const float* addr, float v){
    uint32_t la = (uint32_t)__cvta_generic_to_shared(addr);
    #pragma unroll
    for (int pr = 0; pr < 4; pr++){
        uint32_t raddr;
        asm volatile("mapa.shared::cluster.u32 %0, %1, %2;" : "=r"(raddr) : "r"(la), "r"(pr));
        asm volatile("st.shared::cluster.f32 [%0], %1;" :: "r"(raddr), "f"(v) : "memory");
    }
}

__global__ void __cluster_dims__(4,1,1) __launch_bounds__(256, 1)
lstm_rec_kernel(const float* __restrict__ Whh1,
                const float* __restrict__ Wih2,
                const float* __restrict__ Whh2,
                const float* __restrict__ bih2,
                const float* __restrict__ bhh2,
                float* __restrict__ out)
{
    __shared__ __align__(16) float h1s[2][2][HID];
    __shared__ __align__(16) float h2s[2][2][HID];
    __shared__ float c1s[2][32];
    __shared__ float c2s[2][32];
    __shared__ float ps1[256][2];
    __shared__ float ps2[256][2];
    __shared__ float b2s[128];

    const int tid  = threadIdx.x;
    const int j    = tid & 31;
    const int q    = (tid >> 5) & 3;
    const int half = tid >> 7;
    uint32_t rank;
    asm("mov.u32 %0, %%cluster_ctarank;" : "=r"(rank));
    const int b0   = (blockIdx.x >> 2) * 2;
    const int grow = q * 128 + (int)rank * 32 + j;

    // register-resident packed weight slices (96 b64 = 192 regs)
    unsigned long long w1p[32], w2p[32], w3p[32];
    {
        const float4* p1 = (const float4*)(Whh1 + (size_t)grow * HID + half * 64);
        const float4* p2 = (const float4*)(Wih2 + (size_t)grow * HID + half * 64);
        const float4* p3 = (const float4*)(Whh2 + (size_t)grow * HID + half * 64);
        #pragma unroll
        for (int k = 0; k < 16; k++){
            float4 v1 = p1[k], v2 = p2[k], v3 = p3[k];
            w1p[2*k]   = packf2(v1.x, v1.y);  w1p[2*k+1] = packf2(v1.z, v1.w);
            w2p[2*k]   = packf2(v2.x, v2.y);  w2p[2*k+1] = packf2(v2.z, v2.w);
            w3p[2*k]   = packf2(v3.x, v3.y);  w3p[2*k+1] = packf2(v3.z, v3.w);
        }
    }

    for (int i = tid; i < 2*2*HID; i += 256){
        (&h1s[0][0][0])[i] = 0.f;
        (&h2s[0][0][0])[i] = 0.f;
    }
    if (tid < 64){ c1s[tid>>5][tid&31] = 0.f; c2s[tid>>5][tid&31] = 0.f; }
    if (tid < 128){
        int rr = (tid >> 5) * 128 + (int)rank * 32 + (tid & 31);
        b2s[tid] = bih2[rr] + bhh2[rr];
    }
    __syncthreads();

    // Prologue: layer1(t=0) from x only (h1=c1=0)
    if (tid < 64){
        const int b = tid >> 5, jj = tid & 31;
        const float* xp = g_x1 + ((size_t)0 * BATCH + b0 + b) * GATES + (int)rank * 32 + jj;
        float pre0 = xp[0], pre2 = xp[256], pre3 = xp[384];
        float c = sigmoidf_(pre0) * tanhf(pre2);
        c1s[b][jj] = c;
        float h = sigmoidf_(pre3) * tanhf(c);
        bcast4(&h1s[0][b][(int)rank * 32 + jj], h);
    }
    float xv0 = 0.f, xv1 = 0.f;
    if (half == 0){
        const float* xp = g_x1 + ((size_t)1 * BATCH + b0) * GATES + grow;
        xv0 = xp[0];
        xv1 = xp[GATES];
    }
    asm volatile("barrier.cluster.arrive.aligned;" ::: "memory");
    asm volatile("barrier.cluster.wait.aligned;"   ::: "memory");

    int cur = 0;
    for (int t = 0; t < T_STEPS; t++){
        const int nxt = cur ^ 1;

        // fused packed dot products: layer1(t+1) needs h1(t); layer2(t) needs h1(t), h2(t-1)
        const unsigned long long* A0 = (const unsigned long long*)&h1s[cur][0][half * 64];
        const unsigned long long* A1 = (const unsigned long long*)&h1s[cur][1][half * 64];
        const unsigned long long* D0 = (const unsigned long long*)&h2s[cur][0][half * 64];
        const unsigned long long* D1 = (const unsigned long long*)&h2s[cur][1][half * 64];
        unsigned long long q10 = 0ull, q11 = 0ull, q20 = 0ull, q21 = 0ull;
        #pragma unroll
        for (int kp = 0; kp < 32; kp++){
            unsigned long long a0 = A0[kp], a1 = A1[kp];
            unsigned long long d0 = D0[kp], d1 = D1[kp];
            q10 = fma2(w1p[kp], a0, q10);
            q11 = fma2(w1p[kp], a1, q11);
            q20 = fma2(w2p[kp], a0, q20);
            q21 = fma2(w2p[kp], a1, q21);
            q20 = fma2(w3p[kp], d0, q20);
            q21 = fma2(w3p[kp], d1, q21);
        }
        ps1[tid][0] = hsum2(q10) + xv0;
        ps1[tid][1] = hsum2(q11) + xv1;
        ps2[tid][0] = hsum2(q20);
        ps2[tid][1] = hsum2(q21);
        __syncthreads();

        int   dow  = 0;
        float outv = 0.f;
        if (tid < 64){
            // layer2(t) gates
            const int b = tid >> 5, jj = tid & 31;
            float pre0 = ps2[      jj][b] + ps2[128 + jj][b] + b2s[      jj];
            float pre1 = ps2[ 32 + jj][b] + ps2[160 + jj][b] + b2s[ 32 + jj];
            float pre2 = ps2[ 64 + jj][b] + ps2[192 + jj][b] + b2s[ 64 + jj];
            float pre3 = ps2[ 96 + jj][b] + ps2[224 + jj][b] + b2s[ 96 + jj];
            float c = sigmoidf_(pre1) * c2s[b][jj] + sigmoidf_(pre0) * tanhf(pre2);
            c2s[b][jj] = c;
            float h = sigmoidf_(pre3) * tanhf(c);
            bcast4(&h2s[nxt][b][(int)rank * 32 + jj], h);
            outv = h; dow = 1;
        } else if (tid < 128 && t < T_STEPS - 1){
            // layer1(t+1) gates
            const int u = tid - 64;
            const int b = u >> 5, jj = u & 31;
            float pre0 = ps1[      jj][b] + ps1[128 + jj][b];
            float pre1 = ps1[ 32 + jj][b] + ps1[160 + jj][b];
            float pre2 = ps1[ 64 + jj][b] + ps1[192 + jj][b];
            float pre3 = ps1[ 96 + jj][b] + ps1[224 + jj][b];
            float c = sigmoidf_(pre1) * c1s[b][jj] + sigmoidf_(pre0) * tanhf(pre2);
            c1s[b][jj] = c;
            float h = sigmoidf_(pre3) * tanhf(c);
            bcast4(&h1s[nxt][b][(int)rank * 32 + jj], h);
        }

        asm volatile("barrier.cluster.arrive.aligned;" ::: "memory");

        // hidden in the barrier window: output store + x1 prefetch for t+2
        if (dow)
            out[((size_t)(b0 + (tid >> 5)) * T_STEPS + t) * HID + (int)rank * 32 + (tid & 31)] = outv;
        float nx0 = 0.f, nx1 = 0.f;
        if (half == 0 && t < T_STEPS - 2){
            const float* xp = g_x1 + ((size_t)(t + 2) * BATCH + b0) * GATES + grow;
            nx0 = xp[0];
            nx1 = xp[GATES];
        }

        asm volatile("barrier.cluster.wait.aligned;" ::: "memory");
        xv0 = nx0; xv1 = nx1;
        cur = nxt;
    }
}

// ---------------------------------------------------------------------------
extern "C" void kernel_launch(void* const* d_in, const int* in_sizes, int n_in,
                              void* d_out, int out_size)
{
    (void)in_sizes; (void)n_in; (void)out_size;
    const float* feats = (const float*)d_in[0];
    const float* W_ih1 = (const float*)d_in[1];
    const float* W_hh1 = (const float*)d_in[2];
    const float* b_ih1 = (const float*)d_in[3];
    const float* b_hh1 = (const float*)d_in[4];
    const float* W_ih2 = (const float*)d_in[5];
    const float* W_hh2 = (const float*)d_in[6];
    const float* b_ih2 = (const float*)d_in[7];
    const float* b_hh2 = (const float*)d_in[8];
    float* out = (float*)d_out;

    cudaFuncSetAttribute(x1_gemm_hmma, cudaFuncAttributeMaxDynamicSharedMemorySize, GSMEM);

    dim3 g1(GATES / 128, (BATCH * T_STEPS) / 128);   // (4, 256)
    x1_gemm_hmma<<<g1, 256, GSMEM>>>(feats, W_ih1, b_ih1, b_hh1);

    lstm_rec_kernel<<<128, 256>>>(W_hh1, W_ih2, W_hh2, b_ih2, b_hh2, out);
}